// round 14
// baseline (speedup 1.0000x reference)
#include <cuda_runtime.h>
#include <cuda_fp16.h>
#include <cstdint>

// ---------------------------------------------------------------------------
// DigitConvolutionalModel via mma.sync fp16 GEMMs (single fp16 weights).
// R14: L2/L3 reverted to proven R11 gemm_mma (64x128, atomic fused head).
// gemm_l1 v2: x loaded via cp.async-zfill into fp32 smem stage (double
// buffered), cvt pass -> fp16 A tile. Removes 32-reg xa prefetch; MLP now
// carried by cp.async. conv stays folded into W1'.
// ---------------------------------------------------------------------------

#define BATCH 65536
#define K1P   832    // 784 padded to multiple of 64

// ---- scratch (__device__ globals; no allocations allowed) ----
__device__ __half g_h1[BATCH * 128];
__device__ __half g_h2[BATCH * 512];
__device__ __half g_w1[128 * K1P];      // folded conv+W1, fp16
__device__ __half g_w2[512 * 128];
__device__ __half g_w3[256 * 512];

// ---------------------------------------------------------------------------
// helpers
// ---------------------------------------------------------------------------
__device__ __forceinline__ uint32_t smem_u32(const void* p) {
    uint32_t a;
    asm("{ .reg .u64 t; cvta.to.shared.u64 t, %1; cvt.u32.u64 %0, t; }"
        : "=r"(a) : "l"(p));
    return a;
}
#define SWZ128(off) ((off) ^ (((off) >> 3) & 0x70))

#define CP_ASYNC16(saddr, gptr) \
    asm volatile("cp.async.cg.shared.global [%0], [%1], 16;" \
                 :: "r"(saddr), "l"(gptr) : "memory")
// zfill variant: copies srcsz bytes (0 or 16), zero-fills the rest of 16B
#define CP_ASYNC16Z(saddr, gptr, srcsz) \
    asm volatile("cp.async.cg.shared.global [%0], [%1], 16, %2;" \
                 :: "r"(saddr), "l"(gptr), "r"(srcsz) : "memory")
#define CP_COMMIT() asm volatile("cp.async.commit_group;" ::: "memory")
#define CP_WAIT0()  asm volatile("cp.async.wait_group 0;" ::: "memory")

#define LDSM_X4(r, addr) \
    asm volatile("ldmatrix.sync.aligned.m8n8.x4.shared.b16 {%0,%1,%2,%3}, [%4];" \
                 : "=r"((r)[0]), "=r"((r)[1]), "=r"((r)[2]), "=r"((r)[3]) \
                 : "r"(addr))

#define MMA_F16(d, a, b0, b1) \
    asm volatile("mma.sync.aligned.m16n8k16.row.col.f32.f16.f16.f32 " \
                 "{%0,%1,%2,%3}, {%4,%5,%6,%7}, {%8,%9}, {%0,%1,%2,%3};" \
                 : "+f"((d)[0]), "+f"((d)[1]), "+f"((d)[2]), "+f"((d)[3]) \
                 : "r"((a)[0]), "r"((a)[1]), "r"((a)[2]), "r"((a)[3]), \
                   "r"(b0), "r"(b1))

__device__ __forceinline__ unsigned pack_h2f(float a, float b) {
    return (unsigned)__half_as_ushort(__float2half_rn(a))
         | ((unsigned)__half_as_ushort(__float2half_rn(b)) << 16);
}

// ---------------------------------------------------------------------------
// wfold: W1'[n, pi*28+pj] = sum_{di,dj} W1[n,(pi-di)*26+(pj-dj)]*wc[3di+dj]
// ---------------------------------------------------------------------------
__global__ void wfold_kernel(const float* __restrict__ w1,
                             const float* __restrict__ wc,
                             __half* __restrict__ dst)
{
    int i = blockIdx.x * blockDim.x + threadIdx.x;
    if (i >= 128 * K1P) return;
    int n = i / K1P, p = i - n * K1P;
    float sum = 0.f;
    if (p < 784) {
        int pi = p / 28, pj = p - pi * 28;
        #pragma unroll
        for (int di = 0; di < 3; ++di) {
            #pragma unroll
            for (int dj = 0; dj < 3; ++dj) {
                int oi = pi - di, oj = pj - dj;
                if (oi >= 0 && oi < 26 && oj >= 0 && oj < 26)
                    sum += w1[n * 676 + oi * 26 + oj] * wc[di * 3 + dj];
            }
        }
    }
    dst[i] = __float2half_rn(sum);
}

__global__ void wcast_kernel(const float* __restrict__ src, int N, int Ks, int Kd,
                             __half* __restrict__ dst)
{
    int i = blockIdx.x * blockDim.x + threadIdx.x;
    if (i >= N * Kd) return;
    int n = i / Kd, k = i - n * Kd;
    float v = (k < Ks) ? src[(size_t)n * Ks + k] : 0.f;
    dst[i] = __float2half_rn(v);
}

// ---------------------------------------------------------------------------
// out init: out[m][j] = b4[j]  (atomic partials from L3 land on top)
// ---------------------------------------------------------------------------
__global__ void init_out_kernel(const float* __restrict__ b4,
                                float* __restrict__ out)
{
    int i = blockIdx.x * blockDim.x + threadIdx.x;
    if (i >= BATCH * 10) return;
    int j = i - (i / 10) * 10;
    out[i] = b4[j];
}

// ---------------------------------------------------------------------------
// L1 GEMM v2 (128 threads, 64x128 tile, K=832):
// x (fp32) -> cp.async zfill -> fp32 smem stage (2x16KB, SW128-addressed
// 128B rows) -> cvt pass -> fp16 A tile (8KB) -> ldmatrix. B via cp.async.
// smem: stage [0,32768), Afp16 [32768,40960), B [40960,73728), bias 73728.
// ---------------------------------------------------------------------------
#define L1_STG(b)  ((b) * 16384)
#define L1_A       32768
#define L1_B(b)    (40960 + (b) * 16384)
#define L1_BIAS    73728
#define L1_SMEM    74240

__global__ void __launch_bounds__(128)
gemm_l1(const float* __restrict__ X,
        const __half* __restrict__ B,
        const float* __restrict__ bias,
        __half* __restrict__ outp)
{
    extern __shared__ __align__(1024) char smem[];
    const uint32_t sb = smem_u32(smem);
    const int tid  = threadIdx.x;
    const int wid  = tid >> 5;
    const int lane = tid & 31;
    const int m0   = blockIdx.y * 64;
    const int N    = 128;
    const int K    = K1P;
    float* bs = (float*)(smem + L1_BIAS);

    bs[tid] = bias[tid];

    // ---- x stage loader: 1024 16B-chunks (64 rows x 16), 8 per thread.
    // logical (row, half, j): smem row = row*2+half (128B rows, SW128).
    uint32_t sxOff[8]; size_t gxOff[8]; int colb[8];
    #pragma unroll
    for (int i = 0; i < 8; ++i) {
        const int idx  = tid + 128 * i;
        const int row  = idx >> 4;
        const int ch   = idx & 15;
        const int half = ch >> 3;
        const int j    = ch & 7;
        sxOff[i] = SWZ128((uint32_t)(row * 2 + half) * 128 + j * 16);
        colb[i]  = half * 32 + j * 4;
        gxOff[i] = (size_t)(m0 + row) * 784 + colb[i];
    }

    // ---- B loader (128 rows x 64 fp16 per tile, SW128) ----
    uint32_t soB[8]; size_t gbOff[8];
    #pragma unroll
    for (int i = 0; i < 8; ++i) {
        const int idx = tid + 128 * i;
        const int row = idx >> 3, ch = idx & 7;
        soB[i]  = SWZ128((uint32_t)row * 128 + ch * 16);
        gbOff[i] = (size_t)row * K + ch * 8;
    }

    // cvt-pass output addresses (thread owns one 128B smem row = tid)
    uint32_t aSts[4];
    #pragma unroll
    for (int j4 = 0; j4 < 4; ++j4)
        aSts[j4] = SWZ128((uint32_t)(tid >> 1) * 128
                          + (uint32_t)((tid & 1) * 4 + j4) * 16);

    // ---- prologue: tile 0 ----
    #pragma unroll
    for (int i = 0; i < 8; ++i)
        CP_ASYNC16Z(sb + L1_STG(0) + sxOff[i], X + gxOff[i],
                    (colb[i] < 784) ? 16 : 0);
    #pragma unroll
    for (int i = 0; i < 8; ++i)
        CP_ASYNC16(sb + L1_B(0) + soB[i], B + gbOff[i]);
    CP_COMMIT();

    const int wm = wid & 1;
    const int wn = wid >> 1;
    const int lrow  = lane & 15;
    const int lhalf = (lane >> 4) * 16;

    float acc[2][8][4];
    #pragma unroll
    for (int mi = 0; mi < 2; ++mi)
        #pragma unroll
        for (int nj = 0; nj < 8; ++nj)
            #pragma unroll
            for (int q = 0; q < 4; ++q) acc[mi][nj][q] = 0.f;

    int buf = 0;
    for (int kt = 0; kt < K; kt += 64) {
        CP_WAIT0();
        __syncthreads();

        if (kt + 64 < K) {
            const int nb = buf ^ 1;
            #pragma unroll
            for (int i = 0; i < 8; ++i) {
                const int c = kt + 64 + colb[i];
                CP_ASYNC16Z(sb + L1_STG(nb) + sxOff[i],
                            X + gxOff[i] + (kt + 64), (c < 784) ? 16 : 0);
            }
            #pragma unroll
            for (int i = 0; i < 8; ++i)
                CP_ASYNC16(sb + L1_B(nb) + soB[i], B + gbOff[i] + kt + 64);
            CP_COMMIT();
        }

        // ---- cvt pass: fp32 stage(buf) -> fp16 A tile ----
        {
            const char* stg = smem + L1_STG(buf);
            #pragma unroll
            for (int j4 = 0; j4 < 4; ++j4) {
                float4 p0 = *(const float4*)(stg + SWZ128((uint32_t)tid * 128 + (2 * j4) * 16));
                float4 p1 = *(const float4*)(stg + SWZ128((uint32_t)tid * 128 + (2 * j4 + 1) * 16));
                uint4 v;
                v.x = pack_h2f(p0.x, p0.y);
                v.y = pack_h2f(p0.z, p0.w);
                v.z = pack_h2f(p1.x, p1.y);
                v.w = pack_h2f(p1.z, p1.w);
                *(uint4*)(smem + L1_A + aSts[j4]) = v;
            }
        }
        __syncthreads();

        // ---- MMA on A fp16 + B(buf) ----
        const uint32_t cbA = sb + L1_A;
        const uint32_t cbB = sb + L1_B(buf);
        #pragma unroll
        for (int ks = 0; ks < 4; ++ks) {
            const uint32_t kbyte = ks * 32 + lhalf;
            uint32_t av[2][4];
            #pragma unroll
            for (int mi = 0; mi < 2; ++mi) {
                const uint32_t row = wm * 32 + mi * 16 + lrow;
                LDSM_X4(av[mi], cbA + SWZ128(row * 128 + kbyte));
            }
            uint32_t bv[4][4];
            #pragma unroll
            for (int g = 0; g < 4; ++g) {
                const uint32_t row = wn * 64 + g * 16 + lrow;
                LDSM_X4(bv[g], cbB + SWZ128(row * 128 + kbyte));
            }
            #pragma unroll
            for (int mi = 0; mi < 2; ++mi) {
                #pragma unroll
                for (int nj = 0; nj < 8; ++nj) {
                    const int g = nj >> 1, h = nj & 1;
                    MMA_F16(acc[mi][nj], av[mi], bv[g][h], bv[g][h + 2]);
                }
            }
        }
        buf ^= 1;
    }

    const int qr = lane >> 2;
    const int qc = (lane & 3) * 2;
    #pragma unroll
    for (int mi = 0; mi < 2; ++mi) {
        #pragma unroll
        for (int nj = 0; nj < 8; ++nj) {
            const int col = wn * 64 + nj * 8 + qc;
            const float b0 = bs[col], b1 = bs[col + 1];
            #pragma unroll
            for (int half = 0; half < 2; ++half) {
                const int row = wm * 32 + mi * 16 + qr + half * 8;
                float v0 = fmaxf(acc[mi][nj][half * 2 + 0] + b0, 0.f);
                float v1 = fmaxf(acc[mi][nj][half * 2 + 1] + b1, 0.f);
                *(uint32_t*)(outp + (size_t)(m0 + row) * N + col) =
                    pack_h2f(v0, v1);
            }
        }
    }
}

// ---------------------------------------------------------------------------
// Generic mma.sync fp16 GEMM (R11-proven). CTA 64x128, 128 threads, 4 warps.
// HEAD=true: fused fc(256->10) epilogue with atomicAdd into out.
// ---------------------------------------------------------------------------
#define SM_A    0
#define SM_B    8192
#define BUF_STRIDE 24576
#define SM_BIAS (2 * BUF_STRIDE)
#define SMEM_SZ (SM_BIAS + 512)

template <bool RELU, bool HALF_OUT, bool HEAD>
__global__ void __launch_bounds__(128)
gemm_mma(const __half* __restrict__ A,
         const __half* __restrict__ B,
         const float* __restrict__ bias,
         void* __restrict__ outp,
         int N, int K,
         const float* __restrict__ w4p)
{
    extern __shared__ __align__(1024) char smem[];
    const uint32_t sb = smem_u32(smem);
    const int tid  = threadIdx.x;
    const int wid  = tid >> 5;
    const int lane = tid & 31;
    const int m0   = blockIdx.y * 64;
    const int n0   = blockIdx.x * 128;
    float* bs = (float*)(smem + SM_BIAS);

    bs[tid] = bias[n0 + tid];

    uint32_t soA[4]; size_t gaOff[4];
    #pragma unroll
    for (int i = 0; i < 4; ++i) {
        const int idx = tid + 128 * i;
        const int row = idx >> 3, ch = idx & 7;
        soA[i]  = SWZ128((uint32_t)row * 128 + ch * 16);
        gaOff[i] = (size_t)(m0 + row) * K + ch * 8;
    }
    uint32_t soB[8]; size_t gbOff[8];
    #pragma unroll
    for (int i = 0; i < 8; ++i) {
        const int idx = tid + 128 * i;
        const int row = idx >> 3, ch = idx & 7;
        soB[i]  = SWZ128((uint32_t)row * 128 + ch * 16);
        gbOff[i] = (size_t)(n0 + row) * K + ch * 8;
    }

    #pragma unroll
    for (int i = 0; i < 4; ++i)
        CP_ASYNC16(sb + SM_A + soA[i], A + gaOff[i]);
    #pragma unroll
    for (int i = 0; i < 8; ++i)
        CP_ASYNC16(sb + SM_B + soB[i], B + gbOff[i]);
    CP_COMMIT();

    const int wm = wid & 1;
    const int wn = wid >> 1;
    const int lrow  = lane & 15;
    const int lhalf = (lane >> 4) * 16;

    float acc[2][8][4];
    #pragma unroll
    for (int mi = 0; mi < 2; ++mi)
        #pragma unroll
        for (int nj = 0; nj < 8; ++nj)
            #pragma unroll
            for (int q = 0; q < 4; ++q) acc[mi][nj][q] = 0.f;

    int buf = 0;
    for (int kt = 0; kt < K; kt += 64) {
        CP_WAIT0();
        __syncthreads();

        if (kt + 64 < K) {
            const uint32_t nb = sb + (buf ^ 1) * BUF_STRIDE;
            #pragma unroll
            for (int i = 0; i < 4; ++i)
                CP_ASYNC16(nb + SM_A + soA[i], A + gaOff[i] + kt + 64);
            #pragma unroll
            for (int i = 0; i < 8; ++i)
                CP_ASYNC16(nb + SM_B + soB[i], B + gbOff[i] + kt + 64);
            CP_COMMIT();
        }

        const uint32_t cb = sb + buf * BUF_STRIDE;
        #pragma unroll
        for (int ks = 0; ks < 4; ++ks) {
            const uint32_t kbyte = ks * 32 + lhalf;
            uint32_t av[2][4];
            #pragma unroll
            for (int mi = 0; mi < 2; ++mi) {
                const uint32_t row = wm * 32 + mi * 16 + lrow;
                LDSM_X4(av[mi], cb + SM_A + SWZ128(row * 128 + kbyte));
            }
            uint32_t bv[4][4];
            #pragma unroll
            for (int g = 0; g < 4; ++g) {
                const uint32_t row = wn * 64 + g * 16 + lrow;
                LDSM_X4(bv[g], cb + SM_B + SWZ128(row * 128 + kbyte));
            }
            #pragma unroll
            for (int mi = 0; mi < 2; ++mi) {
                #pragma unroll
                for (int nj = 0; nj < 8; ++nj) {
                    const int g = nj >> 1, h = nj & 1;
                    MMA_F16(acc[mi][nj], av[mi], bv[g][h], bv[g][h + 2]);
                }
            }
        }
        __syncthreads();
        buf ^= 1;
    }

    const int qr = lane >> 2;
    const int qc = (lane & 3) * 2;

    if (HEAD) {
        float* stage = (float*)smem;               // 64 x 128 fp32
        float* w4s   = (float*)(smem + 32768);     // 10 x 128 fp32
        #pragma unroll
        for (int i = tid; i < 1280; i += 128) {
            const int j = i >> 7, ci = i & 127;
            w4s[i] = w4p[j * 256 + n0 + ci];
        }
        #pragma unroll
        for (int mi = 0; mi < 2; ++mi) {
            #pragma unroll
            for (int nj = 0; nj < 8; ++nj) {
                const int col = wn * 64 + nj * 8 + qc;
                const float b0 = bs[col], b1 = bs[col + 1];
                #pragma unroll
                for (int half = 0; half < 2; ++half) {
                    const int row = wm * 32 + mi * 16 + qr + half * 8;
                    stage[row * 128 + col]     = fmaxf(acc[mi][nj][half * 2 + 0] + b0, 0.f);
                    stage[row * 128 + col + 1] = fmaxf(acc[mi][nj][half * 2 + 1] + b1, 0.f);
                }
            }
        }
        __syncthreads();

        float w4r[10][4];
        #pragma unroll
        for (int j = 0; j < 10; ++j)
            #pragma unroll
            for (int t = 0; t < 4; ++t)
                w4r[j][t] = w4s[j * 128 + lane + 32 * t];

        float* outF = (float*)outp;
        #pragma unroll 1
        for (int rr = 0; rr < 16; ++rr) {
            const int row = wid * 16 + rr;
            float xv[4];
            #pragma unroll
            for (int t = 0; t < 4; ++t)
                xv[t] = stage[row * 128 + lane + 32 * t];
            float pj[10];
            #pragma unroll
            for (int j = 0; j < 10; ++j) {
                float s = xv[0] * w4r[j][0];
                s = fmaf(xv[1], w4r[j][1], s);
                s = fmaf(xv[2], w4r[j][2], s);
                s = fmaf(xv[3], w4r[j][3], s);
                #pragma unroll
                for (int off = 16; off > 0; off >>= 1)
                    s += __shfl_xor_sync(0xffffffffu, s, off);
                pj[j] = s;
            }
            if (lane == 0) {
                #pragma unroll
                for (int j = 0; j < 10; ++j)
                    atomicAdd(&outF[(size_t)(m0 + row) * 10 + j], pj[j]);
            }
        }
    } else {
        #pragma unroll
        for (int mi = 0; mi < 2; ++mi) {
            #pragma unroll
            for (int nj = 0; nj < 8; ++nj) {
                const int col = wn * 64 + nj * 8 + qc;
                const float b0 = bs[col], b1 = bs[col + 1];
                #pragma unroll
                for (int half = 0; half < 2; ++half) {
                    const int row = wm * 32 + mi * 16 + qr + half * 8;
                    float v0 = acc[mi][nj][half * 2 + 0] + b0;
                    float v1 = acc[mi][nj][half * 2 + 1] + b1;
                    if (RELU) { v0 = fmaxf(v0, 0.f); v1 = fmaxf(v1, 0.f); }
                    const size_t g = (size_t)(m0 + row) * N + n0 + col;
                    if (HALF_OUT) {
                        *(uint32_t*)((__half*)outp + g) = pack_h2f(v0, v1);
                    } else {
                        *(float2*)((float*)outp + g) = make_float2(v0, v1);
                    }
                }
            }
        }
    }
}

// ---------------------------------------------------------------------------
// Launch
// ---------------------------------------------------------------------------
extern "C" void kernel_launch(void* const* d_in, const int* in_sizes, int n_in,
                              void* d_out, int out_size)
{
    const float* x  = (const float*)d_in[0];
    const float* wc = (const float*)d_in[1];
    const float* w1 = (const float*)d_in[2];
    const float* b1 = (const float*)d_in[3];
    const float* w2 = (const float*)d_in[4];
    const float* b2 = (const float*)d_in[5];
    const float* w3 = (const float*)d_in[6];
    const float* b3 = (const float*)d_in[7];
    const float* w4 = (const float*)d_in[8];
    const float* b4 = (const float*)d_in[9];
    float* out = (float*)d_out;

    __half *h1, *h2, *w1c, *w2c, *w3c;
    cudaGetSymbolAddress((void**)&h1,  g_h1);
    cudaGetSymbolAddress((void**)&h2,  g_h2);
    cudaGetSymbolAddress((void**)&w1c, g_w1);
    cudaGetSymbolAddress((void**)&w2c, g_w2);
    cudaGetSymbolAddress((void**)&w3c, g_w3);

    cudaFuncSetAttribute((const void*)gemm_l1,
                         cudaFuncAttributeMaxDynamicSharedMemorySize, L1_SMEM);
    cudaFuncSetAttribute((const void*)gemm_mma<true, true, false>,
                         cudaFuncAttributeMaxDynamicSharedMemorySize, SMEM_SZ);
    cudaFuncSetAttribute((const void*)gemm_mma<true, false, true>,
                         cudaFuncAttributeMaxDynamicSharedMemorySize, SMEM_SZ);

    // weight prep (tiny)
    wfold_kernel<<<(128 * K1P + 255) / 256, 256>>>(w1, wc, w1c);
    wcast_kernel<<<(512 * 128 + 255) / 256, 256>>>(w2, 512, 128, 128, w2c);
    wcast_kernel<<<(256 * 512 + 255) / 256, 256>>>(w3, 256, 512, 512, w3c);

    // out = b4 broadcast (L3 epilogue atomics accumulate on top)
    init_out_kernel<<<(BATCH * 10 + 255) / 256, 256>>>(b4, out);

    // L1 (conv folded): relu([B,784(x)] x W1'^T) -> h1 (fp16)
    gemm_l1<<<dim3(1, BATCH / 64), 128, L1_SMEM>>>(x, w1c, b1, h1);
    // L2: [B,128] x [512,128]^T -> relu -> h2 (fp16)
    gemm_mma<true, true, false><<<dim3(4, BATCH / 64), 128, SMEM_SZ>>>(
        h1, w2c, b2, h2, 512, 128, nullptr);
    // L3 + head: relu([B,512] x [256,512]^T) @ w4^T + b4 -> out (atomic)
    gemm_mma<true, false, true><<<dim3(2, BATCH / 64), 128, SMEM_SZ>>>(
        h2, w3c, b3, out, 256, 512, w4);
}

// round 15
// speedup vs baseline: 1.1325x; 1.1325x over previous
#include <cuda_runtime.h>
#include <cuda_fp16.h>
#include <cstdint>

// ---------------------------------------------------------------------------
// DigitConvolutionalModel via mma.sync fp16 GEMMs (single fp16 weights).
// R15 = R11 (223us best) + two local edits:
//  (1) gemm_l1 x-prefetch packed to fp16 at load time (32->16 regs held)
//  (2) init_out vectorized (uint4 via 20-float smem pattern)
// Conv folded into W1'; head fused into L3 epilogue via atomicAdd.
// ---------------------------------------------------------------------------

#define BATCH 65536
#define K1P   832    // 784 padded to multiple of 64

// ---- scratch (__device__ globals; no allocations allowed) ----
__device__ __half g_h1[BATCH * 128];
__device__ __half g_h2[BATCH * 512];
__device__ __half g_w1[128 * K1P];      // folded conv+W1, fp16
__device__ __half g_w2[512 * 128];
__device__ __half g_w3[256 * 512];

// ---------------------------------------------------------------------------
// helpers
// ---------------------------------------------------------------------------
__device__ __forceinline__ uint32_t smem_u32(const void* p) {
    uint32_t a;
    asm("{ .reg .u64 t; cvta.to.shared.u64 t, %1; cvt.u32.u64 %0, t; }"
        : "=r"(a) : "l"(p));
    return a;
}
#define SWZ128(off) ((off) ^ (((off) >> 3) & 0x70))

#define CP_ASYNC16(saddr, gptr) \
    asm volatile("cp.async.cg.shared.global [%0], [%1], 16;" \
                 :: "r"(saddr), "l"(gptr) : "memory")
#define CP_COMMIT() asm volatile("cp.async.commit_group;" ::: "memory")
#define CP_WAIT0()  asm volatile("cp.async.wait_group 0;" ::: "memory")

#define LDSM_X4(r, addr) \
    asm volatile("ldmatrix.sync.aligned.m8n8.x4.shared.b16 {%0,%1,%2,%3}, [%4];" \
                 : "=r"((r)[0]), "=r"((r)[1]), "=r"((r)[2]), "=r"((r)[3]) \
                 : "r"(addr))

#define MMA_F16(d, a, b0, b1) \
    asm volatile("mma.sync.aligned.m16n8k16.row.col.f32.f16.f16.f32 " \
                 "{%0,%1,%2,%3}, {%4,%5,%6,%7}, {%8,%9}, {%0,%1,%2,%3};" \
                 : "+f"((d)[0]), "+f"((d)[1]), "+f"((d)[2]), "+f"((d)[3]) \
                 : "r"((a)[0]), "r"((a)[1]), "r"((a)[2]), "r"((a)[3]), \
                   "r"(b0), "r"(b1))

__device__ __forceinline__ unsigned pack_h2f(float a, float b) {
    return (unsigned)__half_as_ushort(__float2half_rn(a))
         | ((unsigned)__half_as_ushort(__float2half_rn(b)) << 16);
}

// ---------------------------------------------------------------------------
// wfold: W1'[n, pi*28+pj] = sum_{di,dj} W1[n,(pi-di)*26+(pj-dj)]*wc[3di+dj]
// ---------------------------------------------------------------------------
__global__ void wfold_kernel(const float* __restrict__ w1,
                             const float* __restrict__ wc,
                             __half* __restrict__ dst)
{
    int i = blockIdx.x * blockDim.x + threadIdx.x;
    if (i >= 128 * K1P) return;
    int n = i / K1P, p = i - n * K1P;
    float sum = 0.f;
    if (p < 784) {
        int pi = p / 28, pj = p - pi * 28;
        #pragma unroll
        for (int di = 0; di < 3; ++di) {
            #pragma unroll
            for (int dj = 0; dj < 3; ++dj) {
                int oi = pi - di, oj = pj - dj;
                if (oi >= 0 && oi < 26 && oj >= 0 && oj < 26)
                    sum += w1[n * 676 + oi * 26 + oj] * wc[di * 3 + dj];
            }
        }
    }
    dst[i] = __float2half_rn(sum);
}

__global__ void wcast_kernel(const float* __restrict__ src, int N, int Ks, int Kd,
                             __half* __restrict__ dst)
{
    int i = blockIdx.x * blockDim.x + threadIdx.x;
    if (i >= N * Kd) return;
    int n = i / Kd, k = i - n * Kd;
    float v = (k < Ks) ? src[(size_t)n * Ks + k] : 0.f;
    dst[i] = __float2half_rn(v);
}

// ---------------------------------------------------------------------------
// out init (vectorized): out[m][j] = b4[j] via uint4 stores.
// 20-float smem pattern (lcm(4,10)); float4 offsets cycle {0,4,8,12,16}.
// ---------------------------------------------------------------------------
__global__ void init_out_kernel(const float* __restrict__ b4,
                                float* __restrict__ out)
{
    __shared__ __align__(16) float pat[20];
    const int tid = threadIdx.x;
    if (tid < 20) pat[tid] = b4[tid % 10];
    __syncthreads();
    const int i = blockIdx.x * blockDim.x + tid;       // float4 index
    if (i < BATCH * 10 / 4) {
        const int o = (i * 4) % 20;
        *(float4*)(out + (size_t)i * 4) = *(const float4*)(pat + o);
    }
}

// ---------------------------------------------------------------------------
// L1 GEMM (128 threads, 64x128, R11 structure): fp32 A (x) via LDG ->
// packed-fp16 register double buffer -> STS; B (W1') via cp.async.
// K=832, logical A width 784. relu, fp16 out.
// ---------------------------------------------------------------------------
#define SM_A    0
#define SM_B    8192
#define BUF_STRIDE 24576
#define SM_BIAS (2 * BUF_STRIDE)
#define SMEM_SZ (SM_BIAS + 512)

__global__ void __launch_bounds__(128)
gemm_l1(const float* __restrict__ X,
        const __half* __restrict__ B,
        const float* __restrict__ bias,
        __half* __restrict__ outp)
{
    extern __shared__ __align__(1024) char smem[];
    const uint32_t sb = smem_u32(smem);
    const int tid  = threadIdx.x;
    const int wid  = tid >> 5;
    const int lane = tid & 31;
    const int m0   = blockIdx.y * 64;
    const int N    = 128;
    const int K    = K1P;
    float* bs = (float*)(smem + SM_BIAS);

    bs[tid] = bias[tid];

    const int arow  = tid >> 1;
    const int aColB = (tid & 1) * 32;
    const float* xrow = X + (size_t)(m0 + arow) * 784;
    uint32_t aSts[4];
    #pragma unroll
    for (int j = 0; j < 4; ++j)
        aSts[j] = SWZ128((uint32_t)arow * 128 + (uint32_t)((tid & 1) * 4 + j) * 16);

    uint32_t soB[8]; size_t gbOff[8];
    #pragma unroll
    for (int i = 0; i < 8; ++i) {
        const int idx = tid + 128 * i;
        const int row = idx >> 3, ch = idx & 7;
        soB[i]  = SWZ128((uint32_t)row * 128 + ch * 16);
        gbOff[i] = (size_t)row * K + ch * 8;
    }

    #pragma unroll
    for (int i = 0; i < 8; ++i)
        CP_ASYNC16(sb + SM_B + soB[i], B + gbOff[i]);
    CP_COMMIT();

    // packed prefetch: each float4 -> uint2 of 4 fp16 (16 regs total)
    uint2 xa[8];
    #pragma unroll
    for (int q = 0; q < 8; ++q) {
        const int col = aColB + q * 4;
        float4 t = (col < 784) ? *(const float4*)(xrow + col)
                               : make_float4(0.f, 0.f, 0.f, 0.f);
        xa[q].x = pack_h2f(t.x, t.y);
        xa[q].y = pack_h2f(t.z, t.w);
    }

    const int wm = wid & 1;
    const int wn = wid >> 1;
    const int lrow  = lane & 15;
    const int lhalf = (lane >> 4) * 16;

    float acc[2][8][4];
    #pragma unroll
    for (int mi = 0; mi < 2; ++mi)
        #pragma unroll
        for (int nj = 0; nj < 8; ++nj)
            #pragma unroll
            for (int q = 0; q < 4; ++q) acc[mi][nj][q] = 0.f;

    int buf = 0;
    for (int kt = 0; kt < K; kt += 64) {
        #pragma unroll
        for (int j = 0; j < 4; ++j) {
            uint4 v = make_uint4(xa[2 * j].x, xa[2 * j].y,
                                 xa[2 * j + 1].x, xa[2 * j + 1].y);
            *(uint4*)(smem + (buf * BUF_STRIDE + SM_A) + aSts[j]) = v;
        }
        CP_WAIT0();
        __syncthreads();

        if (kt + 64 < K) {
            const uint32_t nb = sb + (buf ^ 1) * BUF_STRIDE;
            #pragma unroll
            for (int i = 0; i < 8; ++i)
                CP_ASYNC16(nb + SM_B + soB[i], B + gbOff[i] + kt + 64);
            CP_COMMIT();
            #pragma unroll
            for (int q = 0; q < 8; ++q) {
                const int col = kt + 64 + aColB + q * 4;
                float4 t = (col < 784) ? *(const float4*)(xrow + col)
                                       : make_float4(0.f, 0.f, 0.f, 0.f);
                xa[q].x = pack_h2f(t.x, t.y);
                xa[q].y = pack_h2f(t.z, t.w);
            }
        }

        const uint32_t cb = sb + buf * BUF_STRIDE;
        #pragma unroll
        for (int ks = 0; ks < 4; ++ks) {
            const uint32_t kbyte = ks * 32 + lhalf;
            uint32_t av[2][4];
            #pragma unroll
            for (int mi = 0; mi < 2; ++mi) {
                const uint32_t row = wm * 32 + mi * 16 + lrow;
                LDSM_X4(av[mi], cb + SM_A + SWZ128(row * 128 + kbyte));
            }
            uint32_t bv[4][4];
            #pragma unroll
            for (int g = 0; g < 4; ++g) {
                const uint32_t row = wn * 64 + g * 16 + lrow;
                LDSM_X4(bv[g], cb + SM_B + SWZ128(row * 128 + kbyte));
            }
            #pragma unroll
            for (int mi = 0; mi < 2; ++mi) {
                #pragma unroll
                for (int nj = 0; nj < 8; ++nj) {
                    const int g = nj >> 1, h = nj & 1;
                    MMA_F16(acc[mi][nj], av[mi], bv[g][h], bv[g][h + 2]);
                }
            }
        }
        __syncthreads();
        buf ^= 1;
    }

    const int qr = lane >> 2;
    const int qc = (lane & 3) * 2;
    #pragma unroll
    for (int mi = 0; mi < 2; ++mi) {
        #pragma unroll
        for (int nj = 0; nj < 8; ++nj) {
            const int col = wn * 64 + nj * 8 + qc;
            const float b0 = bs[col], b1 = bs[col + 1];
            #pragma unroll
            for (int half = 0; half < 2; ++half) {
                const int row = wm * 32 + mi * 16 + qr + half * 8;
                float v0 = fmaxf(acc[mi][nj][half * 2 + 0] + b0, 0.f);
                float v1 = fmaxf(acc[mi][nj][half * 2 + 1] + b1, 0.f);
                *(uint32_t*)(outp + (size_t)(m0 + row) * N + col) =
                    pack_h2f(v0, v1);
            }
        }
    }
}

// ---------------------------------------------------------------------------
// Generic mma.sync fp16 GEMM (R11-proven). CTA 64x128, 128 threads, 4 warps.
// HEAD=true: fused fc(256->10) epilogue with atomicAdd into out.
// ---------------------------------------------------------------------------
template <bool RELU, bool HALF_OUT, bool HEAD>
__global__ void __launch_bounds__(128)
gemm_mma(const __half* __restrict__ A,
         const __half* __restrict__ B,
         const float* __restrict__ bias,
         void* __restrict__ outp,
         int N, int K,
         const float* __restrict__ w4p)
{
    extern __shared__ __align__(1024) char smem[];
    const uint32_t sb = smem_u32(smem);
    const int tid  = threadIdx.x;
    const int wid  = tid >> 5;
    const int lane = tid & 31;
    const int m0   = blockIdx.y * 64;
    const int n0   = blockIdx.x * 128;
    float* bs = (float*)(smem + SM_BIAS);

    bs[tid] = bias[n0 + tid];

    uint32_t soA[4]; size_t gaOff[4];
    #pragma unroll
    for (int i = 0; i < 4; ++i) {
        const int idx = tid + 128 * i;
        const int row = idx >> 3, ch = idx & 7;
        soA[i]  = SWZ128((uint32_t)row * 128 + ch * 16);
        gaOff[i] = (size_t)(m0 + row) * K + ch * 8;
    }
    uint32_t soB[8]; size_t gbOff[8];
    #pragma unroll
    for (int i = 0; i < 8; ++i) {
        const int idx = tid + 128 * i;
        const int row = idx >> 3, ch = idx & 7;
        soB[i]  = SWZ128((uint32_t)row * 128 + ch * 16);
        gbOff[i] = (size_t)(n0 + row) * K + ch * 8;
    }

    #pragma unroll
    for (int i = 0; i < 4; ++i)
        CP_ASYNC16(sb + SM_A + soA[i], A + gaOff[i]);
    #pragma unroll
    for (int i = 0; i < 8; ++i)
        CP_ASYNC16(sb + SM_B + soB[i], B + gbOff[i]);
    CP_COMMIT();

    const int wm = wid & 1;
    const int wn = wid >> 1;
    const int lrow  = lane & 15;
    const int lhalf = (lane >> 4) * 16;

    float acc[2][8][4];
    #pragma unroll
    for (int mi = 0; mi < 2; ++mi)
        #pragma unroll
        for (int nj = 0; nj < 8; ++nj)
            #pragma unroll
            for (int q = 0; q < 4; ++q) acc[mi][nj][q] = 0.f;

    int buf = 0;
    for (int kt = 0; kt < K; kt += 64) {
        CP_WAIT0();
        __syncthreads();

        if (kt + 64 < K) {
            const uint32_t nb = sb + (buf ^ 1) * BUF_STRIDE;
            #pragma unroll
            for (int i = 0; i < 4; ++i)
                CP_ASYNC16(nb + SM_A + soA[i], A + gaOff[i] + kt + 64);
            #pragma unroll
            for (int i = 0; i < 8; ++i)
                CP_ASYNC16(nb + SM_B + soB[i], B + gbOff[i] + kt + 64);
            CP_COMMIT();
        }

        const uint32_t cb = sb + buf * BUF_STRIDE;
        #pragma unroll
        for (int ks = 0; ks < 4; ++ks) {
            const uint32_t kbyte = ks * 32 + lhalf;
            uint32_t av[2][4];
            #pragma unroll
            for (int mi = 0; mi < 2; ++mi) {
                const uint32_t row = wm * 32 + mi * 16 + lrow;
                LDSM_X4(av[mi], cb + SM_A + SWZ128(row * 128 + kbyte));
            }
            uint32_t bv[4][4];
            #pragma unroll
            for (int g = 0; g < 4; ++g) {
                const uint32_t row = wn * 64 + g * 16 + lrow;
                LDSM_X4(bv[g], cb + SM_B + SWZ128(row * 128 + kbyte));
            }
            #pragma unroll
            for (int mi = 0; mi < 2; ++mi) {
                #pragma unroll
                for (int nj = 0; nj < 8; ++nj) {
                    const int g = nj >> 1, h = nj & 1;
                    MMA_F16(acc[mi][nj], av[mi], bv[g][h], bv[g][h + 2]);
                }
            }
        }
        __syncthreads();
        buf ^= 1;
    }

    const int qr = lane >> 2;
    const int qc = (lane & 3) * 2;

    if (HEAD) {
        float* stage = (float*)smem;               // 64 x 128 fp32
        float* w4s   = (float*)(smem + 32768);     // 10 x 128 fp32
        #pragma unroll
        for (int i = tid; i < 1280; i += 128) {
            const int j = i >> 7, ci = i & 127;
            w4s[i] = w4p[j * 256 + n0 + ci];
        }
        #pragma unroll
        for (int mi = 0; mi < 2; ++mi) {
            #pragma unroll
            for (int nj = 0; nj < 8; ++nj) {
                const int col = wn * 64 + nj * 8 + qc;
                const float b0 = bs[col], b1 = bs[col + 1];
                #pragma unroll
                for (int half = 0; half < 2; ++half) {
                    const int row = wm * 32 + mi * 16 + qr + half * 8;
                    stage[row * 128 + col]     = fmaxf(acc[mi][nj][half * 2 + 0] + b0, 0.f);
                    stage[row * 128 + col + 1] = fmaxf(acc[mi][nj][half * 2 + 1] + b1, 0.f);
                }
            }
        }
        __syncthreads();

        float w4r[10][4];
        #pragma unroll
        for (int j = 0; j < 10; ++j)
            #pragma unroll
            for (int t = 0; t < 4; ++t)
                w4r[j][t] = w4s[j * 128 + lane + 32 * t];

        float* outF = (float*)outp;
        #pragma unroll 1
        for (int rr = 0; rr < 16; ++rr) {
            const int row = wid * 16 + rr;
            float xv[4];
            #pragma unroll
            for (int t = 0; t < 4; ++t)
                xv[t] = stage[row * 128 + lane + 32 * t];
            float pj[10];
            #pragma unroll
            for (int j = 0; j < 10; ++j) {
                float s = xv[0] * w4r[j][0];
                s = fmaf(xv[1], w4r[j][1], s);
                s = fmaf(xv[2], w4r[j][2], s);
                s = fmaf(xv[3], w4r[j][3], s);
                #pragma unroll
                for (int off = 16; off > 0; off >>= 1)
                    s += __shfl_xor_sync(0xffffffffu, s, off);
                pj[j] = s;
            }
            if (lane == 0) {
                #pragma unroll
                for (int j = 0; j < 10; ++j)
                    atomicAdd(&outF[(size_t)(m0 + row) * 10 + j], pj[j]);
            }
        }
    } else {
        #pragma unroll
        for (int mi = 0; mi < 2; ++mi) {
            #pragma unroll
            for (int nj = 0; nj < 8; ++nj) {
                const int col = wn * 64 + nj * 8 + qc;
                const float b0 = bs[col], b1 = bs[col + 1];
                #pragma unroll
                for (int half = 0; half < 2; ++half) {
                    const int row = wm * 32 + mi * 16 + qr + half * 8;
                    float v0 = acc[mi][nj][half * 2 + 0] + b0;
                    float v1 = acc[mi][nj][half * 2 + 1] + b1;
                    if (RELU) { v0 = fmaxf(v0, 0.f); v1 = fmaxf(v1, 0.f); }
                    const size_t g = (size_t)(m0 + row) * N + n0 + col;
                    if (HALF_OUT) {
                        *(uint32_t*)((__half*)outp + g) = pack_h2f(v0, v1);
                    } else {
                        *(float2*)((float*)outp + g) = make_float2(v0, v1);
                    }
                }
            }
        }
    }
}

// ---------------------------------------------------------------------------
// Launch
// ---------------------------------------------------------------------------
extern "C" void kernel_launch(void* const* d_in, const int* in_sizes, int n_in,
                              void* d_out, int out_size)
{
    const float* x  = (const float*)d_in[0];
    const float* wc = (const float*)d_in[1];
    const float* w1 = (const float*)d_in[2];
    const float* b1 = (const float*)d_in[3];
    const float* w2 = (const float*)d_in[4];
    const float* b2 = (const float*)d_in[5];
    const float* w3 = (const float*)d_in[6];
    const float* b3 = (const float*)d_in[7];
    const float* w4 = (const float*)d_in[8];
    const float* b4 = (const float*)d_in[9];
    float* out = (float*)d_out;

    __half *h1, *h2, *w1c, *w2c, *w3c;
    cudaGetSymbolAddress((void**)&h1,  g_h1);
    cudaGetSymbolAddress((void**)&h2,  g_h2);
    cudaGetSymbolAddress((void**)&w1c, g_w1);
    cudaGetSymbolAddress((void**)&w2c, g_w2);
    cudaGetSymbolAddress((void**)&w3c, g_w3);

    cudaFuncSetAttribute((const void*)gemm_l1,
                         cudaFuncAttributeMaxDynamicSharedMemorySize, SMEM_SZ);
    cudaFuncSetAttribute((const void*)gemm_mma<true, true, false>,
                         cudaFuncAttributeMaxDynamicSharedMemorySize, SMEM_SZ);
    cudaFuncSetAttribute((const void*)gemm_mma<true, false, true>,
                         cudaFuncAttributeMaxDynamicSharedMemorySize, SMEM_SZ);

    // weight prep (tiny)
    wfold_kernel<<<(128 * K1P + 255) / 256, 256>>>(w1, wc, w1c);
    wcast_kernel<<<(512 * 128 + 255) / 256, 256>>>(w2, 512, 128, 128, w2c);
    wcast_kernel<<<(256 * 512 + 255) / 256, 256>>>(w3, 256, 512, 512, w3c);

    // out = b4 broadcast (L3 epilogue atomics accumulate on top)
    init_out_kernel<<<(BATCH * 10 / 4 + 255) / 256, 256>>>(b4, out);

    // L1 (conv folded): relu([B,784(x)] x W1'^T) -> h1 (fp16)
    gemm_l1<<<dim3(1, BATCH / 64), 128, SMEM_SZ>>>(x, w1c, b1, h1);
    // L2: [B,128] x [512,128]^T -> relu -> h2 (fp16)
    gemm_mma<true, true, false><<<dim3(4, BATCH / 64), 128, SMEM_SZ>>>(
        h1, w2c, b2, h2, 512, 128, nullptr);
    // L3 + head: relu([B,512] x [256,512]^T) @ w4^T + b4 -> out (atomic)
    gemm_mma<true, false, true><<<dim3(2, BATCH / 64), 128, SMEM_SZ>>>(
        h2, w3c, b3, out, 256, 512, w4);
}

// round 16
// speedup vs baseline: 1.2081x; 1.0668x over previous
#include <cuda_runtime.h>
#include <cuda_fp16.h>
#include <cstdint>

// ---------------------------------------------------------------------------
// DigitConvolutionalModel via mma.sync fp16 GEMMs (single fp16 weights).
// R16 = exact R11 compute kernels (223us baseline) + peripheral wins only:
//  (1) init_out vectorized (validated 4.5us in R15)
//  (2) single merged prep kernel (wfold + 2 wcasts in one launch)
// Conv folded into W1'; head fused into L3 epilogue via atomicAdd.
// ---------------------------------------------------------------------------

#define BATCH 65536
#define K1P   832    // 784 padded to multiple of 64

// ---- scratch (__device__ globals; no allocations allowed) ----
__device__ __half g_h1[BATCH * 128];
__device__ __half g_h2[BATCH * 512];
__device__ __half g_w1[128 * K1P];      // folded conv+W1, fp16
__device__ __half g_w2[512 * 128];
__device__ __half g_w3[256 * 512];

// ---------------------------------------------------------------------------
// helpers
// ---------------------------------------------------------------------------
__device__ __forceinline__ uint32_t smem_u32(const void* p) {
    uint32_t a;
    asm("{ .reg .u64 t; cvta.to.shared.u64 t, %1; cvt.u32.u64 %0, t; }"
        : "=r"(a) : "l"(p));
    return a;
}
#define SWZ128(off) ((off) ^ (((off) >> 3) & 0x70))

#define CP_ASYNC16(saddr, gptr) \
    asm volatile("cp.async.cg.shared.global [%0], [%1], 16;" \
                 :: "r"(saddr), "l"(gptr) : "memory")
#define CP_COMMIT() asm volatile("cp.async.commit_group;" ::: "memory")
#define CP_WAIT0()  asm volatile("cp.async.wait_group 0;" ::: "memory")

#define LDSM_X4(r, addr) \
    asm volatile("ldmatrix.sync.aligned.m8n8.x4.shared.b16 {%0,%1,%2,%3}, [%4];" \
                 : "=r"((r)[0]), "=r"((r)[1]), "=r"((r)[2]), "=r"((r)[3]) \
                 : "r"(addr))

#define MMA_F16(d, a, b0, b1) \
    asm volatile("mma.sync.aligned.m16n8k16.row.col.f32.f16.f16.f32 " \
                 "{%0,%1,%2,%3}, {%4,%5,%6,%7}, {%8,%9}, {%0,%1,%2,%3};" \
                 : "+f"((d)[0]), "+f"((d)[1]), "+f"((d)[2]), "+f"((d)[3]) \
                 : "r"((a)[0]), "r"((a)[1]), "r"((a)[2]), "r"((a)[3]), \
                   "r"(b0), "r"(b1))

__device__ __forceinline__ unsigned pack_h2f(float a, float b) {
    return (unsigned)__half_as_ushort(__float2half_rn(a))
         | ((unsigned)__half_as_ushort(__float2half_rn(b)) << 16);
}

// ---------------------------------------------------------------------------
// Merged weight prep (one launch):
//   [0, 128*K1P)           : wfold  -> g_w1 (conv folded into W1')
//   [+0, 512*128)          : wcast  -> g_w2
//   [+0, 256*512)          : wcast  -> g_w3
// ---------------------------------------------------------------------------
#define PREP_N1 (128 * K1P)
#define PREP_N2 (512 * 128)
#define PREP_N3 (256 * 512)
#define PREP_TOTAL (PREP_N1 + PREP_N2 + PREP_N3)

__global__ void prep_kernel(const float* __restrict__ w1,
                            const float* __restrict__ wc,
                            const float* __restrict__ w2,
                            const float* __restrict__ w3,
                            __half* __restrict__ d1,
                            __half* __restrict__ d2,
                            __half* __restrict__ d3)
{
    int i = blockIdx.x * blockDim.x + threadIdx.x;
    if (i < PREP_N1) {
        int n = i / K1P, p = i - n * K1P;
        float sum = 0.f;
        if (p < 784) {
            int pi = p / 28, pj = p - pi * 28;
            #pragma unroll
            for (int di = 0; di < 3; ++di) {
                #pragma unroll
                for (int dj = 0; dj < 3; ++dj) {
                    int oi = pi - di, oj = pj - dj;
                    if (oi >= 0 && oi < 26 && oj >= 0 && oj < 26)
                        sum += w1[n * 676 + oi * 26 + oj] * wc[di * 3 + dj];
                }
            }
        }
        d1[i] = __float2half_rn(sum);
    } else if (i < PREP_N1 + PREP_N2) {
        int k = i - PREP_N1;
        d2[k] = __float2half_rn(w2[k]);
    } else if (i < PREP_TOTAL) {
        int k = i - PREP_N1 - PREP_N2;
        d3[k] = __float2half_rn(w3[k]);
    }
}

// ---------------------------------------------------------------------------
// out init (vectorized): out[m][j] = b4[j] via float4 stores.
// 20-float smem pattern (lcm(4,10)); float4 offsets cycle {0,4,8,12,16}.
// ---------------------------------------------------------------------------
__global__ void init_out_kernel(const float* __restrict__ b4,
                                float* __restrict__ out)
{
    __shared__ __align__(16) float pat[20];
    const int tid = threadIdx.x;
    if (tid < 20) pat[tid] = b4[tid % 10];
    __syncthreads();
    const int i = blockIdx.x * blockDim.x + tid;       // float4 index
    if (i < BATCH * 10 / 4) {
        const int o = (i * 4) % 20;
        *(float4*)(out + (size_t)i * 4) = *(const float4*)(pat + o);
    }
}

// ---------------------------------------------------------------------------
// L1 GEMM (exact R11): 128 threads, 64x128 tile, K=832. fp32 A (x) via
// LDG.128 float4 register double buffer -> cvt at STS; B (W1') via cp.async.
// relu, fp16 out.
// ---------------------------------------------------------------------------
#define SM_A    0
#define SM_B    8192
#define BUF_STRIDE 24576
#define SM_BIAS (2 * BUF_STRIDE)
#define SMEM_SZ (SM_BIAS + 512)

__global__ void __launch_bounds__(128)
gemm_l1(const float* __restrict__ X,
        const __half* __restrict__ B,
        const float* __restrict__ bias,
        __half* __restrict__ outp)
{
    extern __shared__ __align__(1024) char smem[];
    const uint32_t sb = smem_u32(smem);
    const int tid  = threadIdx.x;
    const int wid  = tid >> 5;
    const int lane = tid & 31;
    const int m0   = blockIdx.y * 64;
    const int N    = 128;
    const int K    = K1P;
    float* bs = (float*)(smem + SM_BIAS);

    bs[tid] = bias[tid];

    const int arow  = tid >> 1;
    const int aColB = (tid & 1) * 32;
    const float* xrow = X + (size_t)(m0 + arow) * 784;
    uint32_t aSts[4];
    #pragma unroll
    for (int j = 0; j < 4; ++j)
        aSts[j] = SWZ128((uint32_t)arow * 128 + (uint32_t)((tid & 1) * 4 + j) * 16);

    uint32_t soB[8]; size_t gbOff[8];
    #pragma unroll
    for (int i = 0; i < 8; ++i) {
        const int idx = tid + 128 * i;
        const int row = idx >> 3, ch = idx & 7;
        soB[i]  = SWZ128((uint32_t)row * 128 + ch * 16);
        gbOff[i] = (size_t)row * K + ch * 8;
    }

    #pragma unroll
    for (int i = 0; i < 8; ++i)
        CP_ASYNC16(sb + SM_B + soB[i], B + gbOff[i]);
    CP_COMMIT();

    float4 xa[8];
    #pragma unroll
    for (int q = 0; q < 8; ++q) {
        const int col = aColB + q * 4;
        xa[q] = (col < 784) ? *(const float4*)(xrow + col)
                            : make_float4(0.f, 0.f, 0.f, 0.f);
    }

    const int wm = wid & 1;
    const int wn = wid >> 1;
    const int lrow  = lane & 15;
    const int lhalf = (lane >> 4) * 16;

    float acc[2][8][4];
    #pragma unroll
    for (int mi = 0; mi < 2; ++mi)
        #pragma unroll
        for (int nj = 0; nj < 8; ++nj)
            #pragma unroll
            for (int q = 0; q < 4; ++q) acc[mi][nj][q] = 0.f;

    int buf = 0;
    for (int kt = 0; kt < K; kt += 64) {
        #pragma unroll
        for (int j = 0; j < 4; ++j) {
            uint4 v;
            v.x = pack_h2f(xa[2 * j].x,     xa[2 * j].y);
            v.y = pack_h2f(xa[2 * j].z,     xa[2 * j].w);
            v.z = pack_h2f(xa[2 * j + 1].x, xa[2 * j + 1].y);
            v.w = pack_h2f(xa[2 * j + 1].z, xa[2 * j + 1].w);
            *(uint4*)(smem + (buf * BUF_STRIDE + SM_A) + aSts[j]) = v;
        }
        CP_WAIT0();
        __syncthreads();

        if (kt + 64 < K) {
            const uint32_t nb = sb + (buf ^ 1) * BUF_STRIDE;
            #pragma unroll
            for (int i = 0; i < 8; ++i)
                CP_ASYNC16(nb + SM_B + soB[i], B + gbOff[i] + kt + 64);
            CP_COMMIT();
            #pragma unroll
            for (int q = 0; q < 8; ++q) {
                const int col = kt + 64 + aColB + q * 4;
                xa[q] = (col < 784) ? *(const float4*)(xrow + col)
                                    : make_float4(0.f, 0.f, 0.f, 0.f);
            }
        }

        const uint32_t cb = sb + buf * BUF_STRIDE;
        #pragma unroll
        for (int ks = 0; ks < 4; ++ks) {
            const uint32_t kbyte = ks * 32 + lhalf;
            uint32_t av[2][4];
            #pragma unroll
            for (int mi = 0; mi < 2; ++mi) {
                const uint32_t row = wm * 32 + mi * 16 + lrow;
                LDSM_X4(av[mi], cb + SM_A + SWZ128(row * 128 + kbyte));
            }
            uint32_t bv[4][4];
            #pragma unroll
            for (int g = 0; g < 4; ++g) {
                const uint32_t row = wn * 64 + g * 16 + lrow;
                LDSM_X4(bv[g], cb + SM_B + SWZ128(row * 128 + kbyte));
            }
            #pragma unroll
            for (int mi = 0; mi < 2; ++mi) {
                #pragma unroll
                for (int nj = 0; nj < 8; ++nj) {
                    const int g = nj >> 1, h = nj & 1;
                    MMA_F16(acc[mi][nj], av[mi], bv[g][h], bv[g][h + 2]);
                }
            }
        }
        __syncthreads();
        buf ^= 1;
    }

    const int qr = lane >> 2;
    const int qc = (lane & 3) * 2;
    #pragma unroll
    for (int mi = 0; mi < 2; ++mi) {
        #pragma unroll
        for (int nj = 0; nj < 8; ++nj) {
            const int col = wn * 64 + nj * 8 + qc;
            const float b0 = bs[col], b1 = bs[col + 1];
            #pragma unroll
            for (int half = 0; half < 2; ++half) {
                const int row = wm * 32 + mi * 16 + qr + half * 8;
                float v0 = fmaxf(acc[mi][nj][half * 2 + 0] + b0, 0.f);
                float v1 = fmaxf(acc[mi][nj][half * 2 + 1] + b1, 0.f);
                *(uint32_t*)(outp + (size_t)(m0 + row) * N + col) =
                    pack_h2f(v0, v1);
            }
        }
    }
}

// ---------------------------------------------------------------------------
// Generic mma.sync fp16 GEMM (exact R11). CTA 64x128, 128 threads, 4 warps.
// HEAD=true: fused fc(256->10) epilogue with atomicAdd into out.
// ---------------------------------------------------------------------------
template <bool RELU, bool HALF_OUT, bool HEAD>
__global__ void __launch_bounds__(128)
gemm_mma(const __half* __restrict__ A,
         const __half* __restrict__ B,
         const float* __restrict__ bias,
         void* __restrict__ outp,
         int N, int K,
         const float* __restrict__ w4p)
{
    extern __shared__ __align__(1024) char smem[];
    const uint32_t sb = smem_u32(smem);
    const int tid  = threadIdx.x;
    const int wid  = tid >> 5;
    const int lane = tid & 31;
    const int m0   = blockIdx.y * 64;
    const int n0   = blockIdx.x * 128;
    float* bs = (float*)(smem + SM_BIAS);

    bs[tid] = bias[n0 + tid];

    uint32_t soA[4]; size_t gaOff[4];
    #pragma unroll
    for (int i = 0; i < 4; ++i) {
        const int idx = tid + 128 * i;
        const int row = idx >> 3, ch = idx & 7;
        soA[i]  = SWZ128((uint32_t)row * 128 + ch * 16);
        gaOff[i] = (size_t)(m0 + row) * K + ch * 8;
    }
    uint32_t soB[8]; size_t gbOff[8];
    #pragma unroll
    for (int i = 0; i < 8; ++i) {
        const int idx = tid + 128 * i;
        const int row = idx >> 3, ch = idx & 7;
        soB[i]  = SWZ128((uint32_t)row * 128 + ch * 16);
        gbOff[i] = (size_t)(n0 + row) * K + ch * 8;
    }

    #pragma unroll
    for (int i = 0; i < 4; ++i)
        CP_ASYNC16(sb + SM_A + soA[i], A + gaOff[i]);
    #pragma unroll
    for (int i = 0; i < 8; ++i)
        CP_ASYNC16(sb + SM_B + soB[i], B + gbOff[i]);
    CP_COMMIT();

    const int wm = wid & 1;
    const int wn = wid >> 1;
    const int lrow  = lane & 15;
    const int lhalf = (lane >> 4) * 16;

    float acc[2][8][4];
    #pragma unroll
    for (int mi = 0; mi < 2; ++mi)
        #pragma unroll
        for (int nj = 0; nj < 8; ++nj)
            #pragma unroll
            for (int q = 0; q < 4; ++q) acc[mi][nj][q] = 0.f;

    int buf = 0;
    for (int kt = 0; kt < K; kt += 64) {
        CP_WAIT0();
        __syncthreads();

        if (kt + 64 < K) {
            const uint32_t nb = sb + (buf ^ 1) * BUF_STRIDE;
            #pragma unroll
            for (int i = 0; i < 4; ++i)
                CP_ASYNC16(nb + SM_A + soA[i], A + gaOff[i] + kt + 64);
            #pragma unroll
            for (int i = 0; i < 8; ++i)
                CP_ASYNC16(nb + SM_B + soB[i], B + gbOff[i] + kt + 64);
            CP_COMMIT();
        }

        const uint32_t cb = sb + buf * BUF_STRIDE;
        #pragma unroll
        for (int ks = 0; ks < 4; ++ks) {
            const uint32_t kbyte = ks * 32 + lhalf;
            uint32_t av[2][4];
            #pragma unroll
            for (int mi = 0; mi < 2; ++mi) {
                const uint32_t row = wm * 32 + mi * 16 + lrow;
                LDSM_X4(av[mi], cb + SM_A + SWZ128(row * 128 + kbyte));
            }
            uint32_t bv[4][4];
            #pragma unroll
            for (int g = 0; g < 4; ++g) {
                const uint32_t row = wn * 64 + g * 16 + lrow;
                LDSM_X4(bv[g], cb + SM_B + SWZ128(row * 128 + kbyte));
            }
            #pragma unroll
            for (int mi = 0; mi < 2; ++mi) {
                #pragma unroll
                for (int nj = 0; nj < 8; ++nj) {
                    const int g = nj >> 1, h = nj & 1;
                    MMA_F16(acc[mi][nj], av[mi], bv[g][h], bv[g][h + 2]);
                }
            }
        }
        __syncthreads();
        buf ^= 1;
    }

    const int qr = lane >> 2;
    const int qc = (lane & 3) * 2;

    if (HEAD) {
        float* stage = (float*)smem;               // 64 x 128 fp32
        float* w4s   = (float*)(smem + 32768);     // 10 x 128 fp32
        #pragma unroll
        for (int i = tid; i < 1280; i += 128) {
            const int j = i >> 7, ci = i & 127;
            w4s[i] = w4p[j * 256 + n0 + ci];
        }
        #pragma unroll
        for (int mi = 0; mi < 2; ++mi) {
            #pragma unroll
            for (int nj = 0; nj < 8; ++nj) {
                const int col = wn * 64 + nj * 8 + qc;
                const float b0 = bs[col], b1 = bs[col + 1];
                #pragma unroll
                for (int half = 0; half < 2; ++half) {
                    const int row = wm * 32 + mi * 16 + qr + half * 8;
                    stage[row * 128 + col]     = fmaxf(acc[mi][nj][half * 2 + 0] + b0, 0.f);
                    stage[row * 128 + col + 1] = fmaxf(acc[mi][nj][half * 2 + 1] + b1, 0.f);
                }
            }
        }
        __syncthreads();

        float w4r[10][4];
        #pragma unroll
        for (int j = 0; j < 10; ++j)
            #pragma unroll
            for (int t = 0; t < 4; ++t)
                w4r[j][t] = w4s[j * 128 + lane + 32 * t];

        float* outF = (float*)outp;
        #pragma unroll 1
        for (int rr = 0; rr < 16; ++rr) {
            const int row = wid * 16 + rr;
            float xv[4];
            #pragma unroll
            for (int t = 0; t < 4; ++t)
                xv[t] = stage[row * 128 + lane + 32 * t];
            float pj[10];
            #pragma unroll
            for (int j = 0; j < 10; ++j) {
                float s = xv[0] * w4r[j][0];
                s = fmaf(xv[1], w4r[j][1], s);
                s = fmaf(xv[2], w4r[j][2], s);
                s = fmaf(xv[3], w4r[j][3], s);
                #pragma unroll
                for (int off = 16; off > 0; off >>= 1)
                    s += __shfl_xor_sync(0xffffffffu, s, off);
                pj[j] = s;
            }
            if (lane == 0) {
                #pragma unroll
                for (int j = 0; j < 10; ++j)
                    atomicAdd(&outF[(size_t)(m0 + row) * 10 + j], pj[j]);
            }
        }
    } else {
        #pragma unroll
        for (int mi = 0; mi < 2; ++mi) {
            #pragma unroll
            for (int nj = 0; nj < 8; ++nj) {
                const int col = wn * 64 + nj * 8 + qc;
                const float b0 = bs[col], b1 = bs[col + 1];
                #pragma unroll
                for (int half = 0; half < 2; ++half) {
                    const int row = wm * 32 + mi * 16 + qr + half * 8;
                    float v0 = acc[mi][nj][half * 2 + 0] + b0;
                    float v1 = acc[mi][nj][half * 2 + 1] + b1;
                    if (RELU) { v0 = fmaxf(v0, 0.f); v1 = fmaxf(v1, 0.f); }
                    const size_t g = (size_t)(m0 + row) * N + n0 + col;
                    if (HALF_OUT) {
                        *(uint32_t*)((__half*)outp + g) = pack_h2f(v0, v1);
                    } else {
                        *(float2*)((float*)outp + g) = make_float2(v0, v1);
                    }
                }
            }
        }
    }
}

// ---------------------------------------------------------------------------
// Launch
// ---------------------------------------------------------------------------
extern "C" void kernel_launch(void* const* d_in, const int* in_sizes, int n_in,
                              void* d_out, int out_size)
{
    const float* x  = (const float*)d_in[0];
    const float* wc = (const float*)d_in[1];
    const float* w1 = (const float*)d_in[2];
    const float* b1 = (const float*)d_in[3];
    const float* w2 = (const float*)d_in[4];
    const float* b2 = (const float*)d_in[5];
    const float* w3 = (const float*)d_in[6];
    const float* b3 = (const float*)d_in[7];
    const float* w4 = (const float*)d_in[8];
    const float* b4 = (const float*)d_in[9];
    float* out = (float*)d_out;

    __half *h1, *h2, *w1c, *w2c, *w3c;
    cudaGetSymbolAddress((void**)&h1,  g_h1);
    cudaGetSymbolAddress((void**)&h2,  g_h2);
    cudaGetSymbolAddress((void**)&w1c, g_w1);
    cudaGetSymbolAddress((void**)&w2c, g_w2);
    cudaGetSymbolAddress((void**)&w3c, g_w3);

    cudaFuncSetAttribute((const void*)gemm_l1,
                         cudaFuncAttributeMaxDynamicSharedMemorySize, SMEM_SZ);
    cudaFuncSetAttribute((const void*)gemm_mma<true, true, false>,
                         cudaFuncAttributeMaxDynamicSharedMemorySize, SMEM_SZ);
    cudaFuncSetAttribute((const void*)gemm_mma<true, false, true>,
                         cudaFuncAttributeMaxDynamicSharedMemorySize, SMEM_SZ);

    // merged weight prep (one launch) + vectorized out init
    prep_kernel<<<(PREP_TOTAL + 255) / 256, 256>>>(w1, wc, w2, w3, w1c, w2c, w3c);
    init_out_kernel<<<(BATCH * 10 / 4 + 255) / 256, 256>>>(b4, out);

    // L1 (conv folded): relu([B,784(x)] x W1'^T) -> h1 (fp16)
    gemm_l1<<<dim3(1, BATCH / 64), 128, SMEM_SZ>>>(x, w1c, b1, h1);
    // L2: [B,128] x [512,128]^T -> relu -> h2 (fp16)
    gemm_mma<true, true, false><<<dim3(4, BATCH / 64), 128, SMEM_SZ>>>(
        h1, w2c, b2, h2, 512, 128, nullptr);
    // L3 + head: relu([B,512] x [256,512]^T) @ w4^T + b4 -> out (atomic)
    gemm_mma<true, false, true><<<dim3(2, BATCH / 64), 128, SMEM_SZ>>>(
        h2, w3c, b3, out, 256, 512, w4);
}